// round 16
// baseline (speedup 1.0000x reference)
#include <cuda_runtime.h>
#include <cuda_bf16.h>
#include <cuda_fp16.h>
#include <cstdint>

#define NNODES 100000
#define NEDGES 1600000
#define DIN 128
#define DH 128
#define DOUT 64

typedef unsigned long long u64;
typedef unsigned int u32;

// bf16 pitch for MMA operand rows: 136 bf16 = 272 B; banks (4r + c/4) mod 32
#define PITCHB 272
#define AROWS 100032            // 1563 tiles x 64 rows

// ---------------- scratch (device globals; no allocation allowed) -------------
__device__ int    g_deg[NNODES];
__device__ float  g_dinv[NNODES];
__device__ int    g_off[NNODES];
__device__ int    g_cursor[NNODES];
__device__ int2   g_csr[NEDGES];         // packed {src, bitcast(weight)}
__device__ __half g_bufT[(size_t)NNODES * DIN];   // fp16 gather tables (GEMM out)

// pre-split bf16 A images in GEMM smem layout (agg / x-split output)
__device__ __align__(16) char g_Ahi[(size_t)AROWS * PITCHB];
__device__ __align__(16) char g_Alo[(size_t)AROWS * PITCHB];

// pre-split, pre-transposed bf16 weight images: [n][k] rows, 272B pitch
__device__ __align__(16) char g_W1hi[128 * PITCHB], g_W1lo[128 * PITCHB];
__device__ __align__(16) char g_W2hi[128 * PITCHB], g_W2lo[128 * PITCHB];
__device__ __align__(16) char g_W3hi[64 * PITCHB],  g_W3lo[64 * PITCHB];

#define SCAN_CHUNK 1024
#define SCAN_BLOCKS 98
__device__ int g_bsum[SCAN_BLOCKS];

// ---------------- helpers ------------------------------------------------------
__device__ __forceinline__ u32 smem_u32(const void* p) {
    u32 a;
    asm("{ .reg .u64 t; cvta.to.shared.u64 t, %1; cvt.u32.u64 %0, t; }" : "=r"(a) : "l"(p));
    return a;
}

__device__ __forceinline__ void split4(float4 v, u64& hi, u64& lo) {
    __nv_bfloat16 hx = __float2bfloat16_rn(v.x);
    __nv_bfloat16 hy = __float2bfloat16_rn(v.y);
    __nv_bfloat16 hz = __float2bfloat16_rn(v.z);
    __nv_bfloat16 hw = __float2bfloat16_rn(v.w);
    __nv_bfloat16 lx = __float2bfloat16_rn(v.x - __bfloat162float(hx));
    __nv_bfloat16 ly = __float2bfloat16_rn(v.y - __bfloat162float(hy));
    __nv_bfloat16 lz = __float2bfloat16_rn(v.z - __bfloat162float(hz));
    __nv_bfloat16 lw = __float2bfloat16_rn(v.w - __bfloat162float(hw));
    hi = (u64)__bfloat16_as_ushort(hx) | ((u64)__bfloat16_as_ushort(hy) << 16)
       | ((u64)__bfloat16_as_ushort(hz) << 32) | ((u64)__bfloat16_as_ushort(hw) << 48);
    lo = (u64)__bfloat16_as_ushort(lx) | ((u64)__bfloat16_as_ushort(ly) << 16)
       | ((u64)__bfloat16_as_ushort(lz) << 32) | ((u64)__bfloat16_as_ushort(lw) << 48);
}

#define MMA16816(c, a, b) \
    asm volatile( \
        "mma.sync.aligned.m16n8k16.row.col.f32.bf16.bf16.f32 " \
        "{%0,%1,%2,%3}, {%4,%5,%6,%7}, {%8,%9}, {%0,%1,%2,%3};" \
        : "+f"((c)[0]), "+f"((c)[1]), "+f"((c)[2]), "+f"((c)[3]) \
        : "r"((a)[0]), "r"((a)[1]), "r"((a)[2]), "r"((a)[3]), \
          "r"((b)[0]), "r"((b)[1]))

#define LDSM_X4(r0, r1, r2, r3, addr) \
    asm volatile("ldmatrix.sync.aligned.m8n8.x4.shared.b16 {%0,%1,%2,%3}, [%4];" \
                 : "=r"(r0), "=r"(r1), "=r"(r2), "=r"(r3) : "r"(addr))

#define CP_ASYNC16(smem_addr, gptr) \
    asm volatile("cp.async.cg.shared.global [%0], [%1], 16;" \
                 :: "r"(smem_addr), "l"(gptr) : "memory")
#define CP_ASYNC_WAIT_ALL() \
    asm volatile("cp.async.commit_group;\n\tcp.async.wait_group 0;" ::: "memory")

// ---------------- fused init + weight prep + x-split (1 launch) ----------------
__device__ __forceinline__ void prepW_body(const float* __restrict__ W,
                                           char* __restrict__ hi_img,
                                           char* __restrict__ lo_img,
                                           int i, int BN) {
    if (i >= BN * 32) return;
    int n = i >> 5;
    int k4 = (i & 31) * 4;
    float4 v;
    v.x = W[(size_t)(k4 + 0) * BN + n];
    v.y = W[(size_t)(k4 + 1) * BN + n];
    v.z = W[(size_t)(k4 + 2) * BN + n];
    v.w = W[(size_t)(k4 + 3) * BN + n];
    u64 hi, lo;
    split4(v, hi, lo);
    size_t off = (size_t)n * PITCHB + (size_t)k4 * 2;
    *reinterpret_cast<u64*>(hi_img + off) = hi;
    *reinterpret_cast<u64*>(lo_img + off) = lo;
}

#define NODE_BLOCKS 391   // ceil(100000/256)
#define XSPLIT_BLOCKS 12500   // 100000*32 float4 / 256
__global__ void k_prep_init(const float* __restrict__ W1, const float* __restrict__ W2,
                            const float* __restrict__ W3, const float* __restrict__ x) {
    int b = blockIdx.x;
    int tid = threadIdx.x;
    if (b < NODE_BLOCKS) {
        int v = b * 256 + tid;
        if (v < NNODES) { g_deg[v] = 1; g_cursor[v] = 0; }
    } else if (b < NODE_BLOCKS + 16) {
        prepW_body(W1, g_W1hi, g_W1lo, (b - NODE_BLOCKS) * 256 + tid, 128);
    } else if (b < NODE_BLOCKS + 32) {
        prepW_body(W2, g_W2hi, g_W2lo, (b - NODE_BLOCKS - 16) * 256 + tid, 128);
    } else if (b < NODE_BLOCKS + 40) {
        prepW_body(W3, g_W3hi, g_W3lo, (b - NODE_BLOCKS - 32) * 256 + tid, 64);
    } else {
        int i = (b - (NODE_BLOCKS + 40)) * 256 + tid;
        if (i < NNODES * 32) {
            int row = i >> 5;
            int c4 = (i & 31) * 4;
            float4 v = *reinterpret_cast<const float4*>(&x[(size_t)row * 128 + c4]);
            u64 hi, lo;
            split4(v, hi, lo);
            size_t off = (size_t)row * PITCHB + (size_t)c4 * 2;
            *reinterpret_cast<u64*>(g_Ahi + off) = hi;
            *reinterpret_cast<u64*>(g_Alo + off) = lo;
        }
    }
}

// ---------------- mma.sync GEMM v6: all-cp.async load, no split --------------
// C[M,BN] = A[M,128] @ W[128,BN] from pre-split bf16 images; fused 3-term split.
// 512 thr / 16 warps / BM=64, 2 CTA/SM, warp tile 16 x (BN/4); fp16 epilogue.
template <int BN>
__global__ __launch_bounds__(512, 2) void k_mma(const char* __restrict__ AhiImg,
                                                const char* __restrict__ AloImg,
                                                const char* __restrict__ BhiImg,
                                                const char* __restrict__ BloImg,
                                                __half* __restrict__ C, int M) {
    extern __shared__ char smem[];
    constexpr int A_BYTES = 64 * PITCHB;      // 17408
    constexpr int B_BYTES = BN * PITCHB;
    char* sAhi = smem;
    char* sAlo = smem + A_BYTES;
    char* sBhi = smem + 2 * A_BYTES;
    char* sBlo = sBhi + B_BYTES;

    int tid = threadIdx.x;
    int blockRow = blockIdx.x * 64;

    // pure cp.async load phase: A tile (pre-split images) + B images
    {
        u32 dAh = smem_u32(sAhi), dAl = smem_u32(sAlo);
        const char* gAh = AhiImg + (size_t)blockRow * PITCHB;
        const char* gAl = AloImg + (size_t)blockRow * PITCHB;
        for (int i = tid; i < A_BYTES / 16; i += 512) {   // 1088
            CP_ASYNC16(dAh + i * 16, gAh + (size_t)i * 16);
            CP_ASYNC16(dAl + i * 16, gAl + (size_t)i * 16);
        }
        u32 dBh = smem_u32(sBhi), dBl = smem_u32(sBlo);
        for (int i = tid; i < BN * 17; i += 512) {        // B_BYTES/16
            CP_ASYNC16(dBh + i * 16, BhiImg + (size_t)i * 16);
            CP_ASYNC16(dBl + i * 16, BloImg + (size_t)i * 16);
        }
    }
    CP_ASYNC_WAIT_ALL();
    __syncthreads();

    int wid = tid >> 5, lane = tid & 31;
    int g = lane >> 2, t = lane & 3;
    constexpr int WN = BN / 4;        // 32 (BN=128) or 16 (BN=64)
    constexpr int NT = WN / 8;        // 4 or 2
    constexpr int NPAIR = (NT / 2 > 0) ? NT / 2 : 1;  // 2 or 1
    int wm = wid & 3, wn = wid >> 2;
    int rowbase = wm * 16;
    int colbase = wn * WN;

    // ldmatrix lane addressing: row = lane%16, +16B column select for lane>=16
    u32 lrow = lane & 15;
    u32 lsel = (lane >> 4) << 4;
    u32 aHiB = smem_u32(sAhi) + (rowbase + lrow) * PITCHB + lsel;
    u32 aLoB = aHiB + A_BYTES;
    u32 bHiB[NPAIR], bLoB[NPAIR];
#pragma unroll
    for (int p = 0; p < NPAIR; p++) {
        bHiB[p] = smem_u32(sBhi) + (colbase + p * 16 + lrow) * PITCHB + lsel;
        bLoB[p] = bHiB[p] + B_BYTES;
    }

    float c[NT][4];
#pragma unroll
    for (int nt = 0; nt < NT; nt++)
#pragma unroll
        for (int j = 0; j < 4; j++) c[nt][j] = 0.f;

#pragma unroll
    for (int k0 = 0; k0 < 128; k0 += 16) {
        u32 koff = k0 * 2;
        u32 ah[4], al[4];
        LDSM_X4(ah[0], ah[1], ah[2], ah[3], aHiB + koff);
        LDSM_X4(al[0], al[1], al[2], al[3], aLoB + koff);
        u32 bh[NT][2], bl[NT][2];
#pragma unroll
        for (int p = 0; p < NPAIR; p++) {
            u32 r0, r1, r2, r3;
            LDSM_X4(r0, r1, r2, r3, bHiB[p] + koff);
            bh[2 * p + 0][0] = r0; bh[2 * p + 1][0] = r1;
            bh[2 * p + 0][1] = r2; bh[2 * p + 1][1] = r3;
            LDSM_X4(r0, r1, r2, r3, bLoB[p] + koff);
            bl[2 * p + 0][0] = r0; bl[2 * p + 1][0] = r1;
            bl[2 * p + 0][1] = r2; bl[2 * p + 1][1] = r3;
        }
        // 3 terms: hi*hi, hi*lo, lo*hi
#pragma unroll
        for (int nt = 0; nt < NT; nt++) MMA16816(c[nt], ah, bh[nt]);
#pragma unroll
        for (int nt = 0; nt < NT; nt++) MMA16816(c[nt], ah, bl[nt]);
#pragma unroll
        for (int nt = 0; nt < NT; nt++) MMA16816(c[nt], al, bh[nt]);
    }

    // epilogue: fp16 half2 stores (rows g and g+8 of warp tile)
    int row = blockRow + rowbase + g;
#pragma unroll
    for (int nt = 0; nt < NT; nt++) {
        int col = colbase + nt * 8 + 2 * t;
        if (row < M)
            *reinterpret_cast<__half2*>(&C[(size_t)row * BN + col]) =
                __floats2half2_rn(c[nt][0], c[nt][1]);
        if (row + 8 < M)
            *reinterpret_cast<__half2*>(&C[(size_t)(row + 8) * BN + col]) =
                __floats2half2_rn(c[nt][2], c[nt][3]);
    }
}

// ---------------- CSR build ---------------------------------------------------
__global__ void k_count(const int* __restrict__ dst) {
    int e = blockIdx.x * blockDim.x + threadIdx.x;
    if (e < NEDGES) atomicAdd(&g_deg[dst[e]], 1);
}
__global__ void k_scan_block(void) {
    __shared__ int wsum[8];
    int tid = threadIdx.x;
    int base = blockIdx.x * SCAN_CHUNK + tid * 4;
    int v[4];
#pragma unroll
    for (int i = 0; i < 4; i++) {
        int idx = base + i;
        v[i] = (idx < NNODES) ? (g_deg[idx] - 1) : 0;
        if (idx < NNODES) g_dinv[idx] = rsqrtf((float)(v[i] + 1));
    }
    int e0 = 0, e1 = v[0], e2 = v[0] + v[1], e3 = v[0] + v[1] + v[2];
    int tot = e3 + v[3];
    int lane = tid & 31, wid = tid >> 5;
    int x = tot;
#pragma unroll
    for (int off = 1; off < 32; off <<= 1) {
        int y = __shfl_up_sync(0xFFFFFFFFu, x, off);
        if (lane >= off) x += y;
    }
    if (lane == 31) wsum[wid] = x;
    __syncthreads();
    if (wid == 0) {
        int tt = (lane < 8) ? wsum[lane] : 0;
        int xx = tt;
#pragma unroll
        for (int off = 1; off < 8; off <<= 1) {
            int y = __shfl_up_sync(0xFFFFFFFFu, xx, off);
            if (lane >= off) xx += y;
        }
        if (lane < 8) wsum[lane] = xx - tt;
    }
    __syncthreads();
    int texc = wsum[wid] + (x - tot);
    if (base + 0 < NNODES) g_off[base + 0] = texc + e0;
    if (base + 1 < NNODES) g_off[base + 1] = texc + e1;
    if (base + 2 < NNODES) g_off[base + 2] = texc + e2;
    if (base + 3 < NNODES) g_off[base + 3] = texc + e3;
    if (tid == blockDim.x - 1) g_bsum[blockIdx.x] = texc + tot;
}
// scan_add with inlined top-level prefix (each block sums its g_bsum prefix)
__global__ void k_scan_add(void) {
    __shared__ int ssum;
    int tid = threadIdx.x;
    int bid = blockIdx.x;
    if (tid == 0) ssum = 0;
    __syncthreads();
    int p = 0;
    for (int j = tid; j < bid; j += 256) p += g_bsum[j];
    if (p) atomicAdd(&ssum, p);
    __syncthreads();
    int add = ssum;
    int base = bid * SCAN_CHUNK + tid * 4;
#pragma unroll
    for (int i = 0; i < 4; i++) {
        int idx = base + i;
        if (idx < NNODES) g_off[idx] += add;
    }
}
__global__ void k_scatter(const int* __restrict__ src, const int* __restrict__ dst) {
    int e = blockIdx.x * blockDim.x + threadIdx.x;
    if (e >= NEDGES) return;
    int s = src[e], d = dst[e];
    int pos = g_off[d] + atomicAdd(&g_cursor[d], 1);
    g_csr[pos] = make_int2(s, __float_as_int(g_dinv[s] * g_dinv[d]));
}

// ---------------- Aggregation: fp16 gather, fp32 accumulate ------------------
// DIM==128: writes pre-split bf16 hi/lo images (next GEMM input). DIM==64: fp32 out.
__device__ __forceinline__ float4 h4f(uint2 u) {
    float2 a = __half22float2(*reinterpret_cast<__half2*>(&u.x));
    float2 b = __half22float2(*reinterpret_cast<__half2*>(&u.y));
    return make_float4(a.x, a.y, b.x, b.y);
}
__device__ __forceinline__ float2 h2f(u32 u) {
    return __half22float2(*reinterpret_cast<__half2*>(&u));
}

template <int DIM, bool RELU>
__global__ __launch_bounds__(256) void k_agg(const __half* __restrict__ h,
                                             const float* __restrict__ bias,
                                             char* __restrict__ outHi,
                                             char* __restrict__ outLo,
                                             float* __restrict__ out) {
    int warp = (blockIdx.x * blockDim.x + threadIdx.x) >> 5;
    if (warp >= NNODES) return;
    int lane = threadIdx.x & 31;

    float dv = g_dinv[warp];
    float wself = dv * dv;
    int beg = g_off[warp];
    int end = beg + (g_deg[warp] - 1);
    const int2* __restrict__ cp = g_csr;

    if (DIM == 128) {
        const uint2* hp = reinterpret_cast<const uint2*>(h);   // 8B = 4 halfs/lane
        float4 sv = h4f(hp[(size_t)warp * 32 + lane]);
        float ax = sv.x * wself, ay = sv.y * wself, az = sv.z * wself, aw = sv.w * wself;
        int e = beg;
        for (; e + 3 < end; e += 4) {
            int2 p0 = cp[e], p1 = cp[e + 1], p2 = cp[e + 2], p3 = cp[e + 3];
            float w0 = __int_as_float(p0.y), w1 = __int_as_float(p1.y);
            float w2 = __int_as_float(p2.y), w3 = __int_as_float(p3.y);
            float4 v0 = h4f(hp[(size_t)p0.x * 32 + lane]);
            float4 v1 = h4f(hp[(size_t)p1.x * 32 + lane]);
            float4 v2 = h4f(hp[(size_t)p2.x * 32 + lane]);
            float4 v3 = h4f(hp[(size_t)p3.x * 32 + lane]);
            ax += v0.x * w0 + v1.x * w1 + v2.x * w2 + v3.x * w3;
            ay += v0.y * w0 + v1.y * w1 + v2.y * w2 + v3.y * w3;
            az += v0.z * w0 + v1.z * w1 + v2.z * w2 + v3.z * w3;
            aw += v0.w * w0 + v1.w * w1 + v2.w * w2 + v3.w * w3;
        }
        for (; e < end; e++) {
            int2 p0 = cp[e];
            float w0 = __int_as_float(p0.y);
            float4 v0 = h4f(hp[(size_t)p0.x * 32 + lane]);
            ax += v0.x * w0; ay += v0.y * w0; az += v0.z * w0; aw += v0.w * w0;
        }
        float4 b4 = reinterpret_cast<const float4*>(bias)[lane];
        ax += b4.x; ay += b4.y; az += b4.z; aw += b4.w;
        if (RELU) {
            ax = fmaxf(ax, 0.f); ay = fmaxf(ay, 0.f);
            az = fmaxf(az, 0.f); aw = fmaxf(aw, 0.f);
        }
        // write pre-split bf16 hi/lo image rows (GEMM smem layout)
        u64 hi, lo;
        split4(make_float4(ax, ay, az, aw), hi, lo);
        size_t off = (size_t)warp * PITCHB + (size_t)lane * 8;
        *reinterpret_cast<u64*>(outHi + off) = hi;
        *reinterpret_cast<u64*>(outLo + off) = lo;
    } else {  // DIM == 64: final layer, fp32 output
        const u32* hp = reinterpret_cast<const u32*>(h);       // 4B = 2 halfs/lane
        float2 sv = h2f(hp[(size_t)warp * 32 + lane]);
        float ax = sv.x * wself, ay = sv.y * wself;
        int e = beg;
        for (; e + 3 < end; e += 4) {
            int2 p0 = cp[e], p1 = cp[e + 1], p2 = cp[e + 2], p3 = cp[e + 3];
            float w0 = __int_as_float(p0.y), w1 = __int_as_float(p1.y);
            float w2 = __int_as_float(p2.y), w3 = __int_as_float(p3.y);
            float2 v0 = h2f(hp[(size_t)p0.x * 32 + lane]);
            float2 v1 = h2f(hp[(size_t)p1.x * 32 + lane]);
            float2 v2 = h2f(hp[(size_t)p2.x * 32 + lane]);
            float2 v3 = h2f(hp[(size_t)p3.x * 32 + lane]);
            ax += v0.x * w0 + v1.x * w1 + v2.x * w2 + v3.x * w3;
            ay += v0.y * w0 + v1.y * w1 + v2.y * w2 + v3.y * w3;
        }
        for (; e < end; e++) {
            int2 p0 = cp[e];
            float w0 = __int_as_float(p0.y);
            float2 v0 = h2f(hp[(size_t)p0.x * 32 + lane]);
            ax += v0.x * w0; ay += v0.y * w0;
        }
        float2 b2 = reinterpret_cast<const float2*>(bias)[lane];
        ax += b2.x; ay += b2.y;
        if (RELU) { ax = fmaxf(ax, 0.f); ay = fmaxf(ay, 0.f); }
        float2 o; o.x = ax; o.y = ay;
        reinterpret_cast<float2*>(out)[(size_t)warp * 32 + lane] = o;
    }
}

// ---------------- launch ------------------------------------------------------
extern "C" void kernel_launch(void* const* d_in, const int* in_sizes, int n_in,
                              void* d_out, int out_size) {
    const float* x  = (const float*)d_in[0];
    const int*   ei = (const int*)d_in[1];
    const float* W1 = (const float*)d_in[2];
    const float* b1 = (const float*)d_in[3];
    const float* W2 = (const float*)d_in[4];
    const float* b2 = (const float*)d_in[5];
    const float* W3 = (const float*)d_in[6];
    const float* b3 = (const float*)d_in[7];
    float* out = (float*)d_out;

    const int* src = ei;
    const int* dst = ei + NEDGES;

    __half* bufT; cudaGetSymbolAddress((void**)&bufT, g_bufT);
    char *aHi, *aLo;
    cudaGetSymbolAddress((void**)&aHi, g_Ahi);
    cudaGetSymbolAddress((void**)&aLo, g_Alo);
    char *w1h, *w1l, *w2h, *w2l, *w3h, *w3l;
    cudaGetSymbolAddress((void**)&w1h, g_W1hi); cudaGetSymbolAddress((void**)&w1l, g_W1lo);
    cudaGetSymbolAddress((void**)&w2h, g_W2hi); cudaGetSymbolAddress((void**)&w2l, g_W2lo);
    cudaGetSymbolAddress((void**)&w3h, g_W3hi); cudaGetSymbolAddress((void**)&w3l, g_W3lo);

    const int SMEM128 = 2 * 64 * PITCHB + 2 * 128 * PITCHB;  // 104448
    const int SMEM64  = 2 * 64 * PITCHB + 2 * 64 * PITCHB;   //  69632
    cudaFuncSetAttribute(k_mma<128>, cudaFuncAttributeMaxDynamicSharedMemorySize, SMEM128);
    cudaFuncSetAttribute(k_mma<64>,  cudaFuncAttributeMaxDynamicSharedMemorySize, SMEM64);

    const int TB = 256;
    int edgeBlocks = (NEDGES + TB - 1) / TB;
    int gemmBlocks = (NNODES + 63) / 64;     // 1563
    int aggBlocks  = (NNODES + 7) / 8;
    int prepBlocks = NODE_BLOCKS + 40 + XSPLIT_BLOCKS;  // 12931

    // 11 launches; k_mma<128> is the 4th -> the ncu-profiled launch
    k_prep_init<<<prepBlocks, TB>>>(W1, W2, W3, x);
    k_count<<<edgeBlocks, TB>>>(dst);
    k_scan_block<<<SCAN_BLOCKS, TB>>>();                      // also fills g_dinv
    k_mma<128><<<gemmBlocks, 512, SMEM128>>>(aHi, aLo, w1h, w1l, bufT, NNODES);  // profiled
    k_scan_add<<<SCAN_BLOCKS, TB>>>();
    k_scatter<<<edgeBlocks, TB>>>(src, dst);

    k_agg<128, true><<<aggBlocks, TB>>>(bufT, b1, aHi, aLo, nullptr);
    k_mma<128><<<gemmBlocks, 512, SMEM128>>>(aHi, aLo, w2h, w2l, bufT, NNODES);
    k_agg<128, true><<<aggBlocks, TB>>>(bufT, b2, aHi, aLo, nullptr);
    k_mma<64><<<gemmBlocks, 512, SMEM64>>>(aHi, aLo, w3h, w3l, bufT, NNODES);
    k_agg<64, false><<<aggBlocks, TB>>>(bufT, b3, nullptr, nullptr, out);
}

// round 17
// speedup vs baseline: 1.4833x; 1.4833x over previous
#include <cuda_runtime.h>
#include <cuda_bf16.h>
#include <cuda_fp16.h>
#include <cstdint>

#define NNODES 100000
#define NEDGES 1600000
#define DIN 128
#define DH 128
#define DOUT 64

typedef unsigned long long u64;
typedef unsigned int u32;

// bf16 pitch for MMA operand rows: 136 bf16 = 272 B; banks (4r + c/4) mod 32
#define PITCHB 272

// ---------------- scratch (device globals; no allocation allowed) -------------
__device__ int    g_deg[NNODES];
__device__ float  g_dinv[NNODES];
__device__ int    g_off[NNODES];
__device__ int    g_cursor[NNODES];
__device__ int2   g_csr[NEDGES];         // packed {src, bitcast(weight)}
__device__ __half g_bufT[(size_t)NNODES * DIN];   // fp16 gather tables (GEMM out)
__device__ float  g_bufB[(size_t)NNODES * DIN];   // fp32 node vectors (agg out)

// pre-split, pre-transposed bf16 weight images: [n][k] rows, 272B pitch
__device__ __align__(16) char g_W1hi[128 * PITCHB], g_W1lo[128 * PITCHB];
__device__ __align__(16) char g_W2hi[128 * PITCHB], g_W2lo[128 * PITCHB];
__device__ __align__(16) char g_W3hi[64 * PITCHB],  g_W3lo[64 * PITCHB];

#define SCAN_CHUNK 1024
#define SCAN_BLOCKS 98
__device__ int g_bsum[SCAN_BLOCKS];

// ---------------- helpers ------------------------------------------------------
__device__ __forceinline__ u32 smem_u32(const void* p) {
    u32 a;
    asm("{ .reg .u64 t; cvta.to.shared.u64 t, %1; cvt.u32.u64 %0, t; }" : "=r"(a) : "l"(p));
    return a;
}

__device__ __forceinline__ void split4(float4 v, u64& hi, u64& lo) {
    __nv_bfloat16 hx = __float2bfloat16_rn(v.x);
    __nv_bfloat16 hy = __float2bfloat16_rn(v.y);
    __nv_bfloat16 hz = __float2bfloat16_rn(v.z);
    __nv_bfloat16 hw = __float2bfloat16_rn(v.w);
    __nv_bfloat16 lx = __float2bfloat16_rn(v.x - __bfloat162float(hx));
    __nv_bfloat16 ly = __float2bfloat16_rn(v.y - __bfloat162float(hy));
    __nv_bfloat16 lz = __float2bfloat16_rn(v.z - __bfloat162float(hz));
    __nv_bfloat16 lw = __float2bfloat16_rn(v.w - __bfloat162float(hw));
    hi = (u64)__bfloat16_as_ushort(hx) | ((u64)__bfloat16_as_ushort(hy) << 16)
       | ((u64)__bfloat16_as_ushort(hz) << 32) | ((u64)__bfloat16_as_ushort(hw) << 48);
    lo = (u64)__bfloat16_as_ushort(lx) | ((u64)__bfloat16_as_ushort(ly) << 16)
       | ((u64)__bfloat16_as_ushort(lz) << 32) | ((u64)__bfloat16_as_ushort(lw) << 48);
}

#define MMA16816(c, a, b) \
    asm volatile( \
        "mma.sync.aligned.m16n8k16.row.col.f32.bf16.bf16.f32 " \
        "{%0,%1,%2,%3}, {%4,%5,%6,%7}, {%8,%9}, {%0,%1,%2,%3};" \
        : "+f"((c)[0]), "+f"((c)[1]), "+f"((c)[2]), "+f"((c)[3]) \
        : "r"((a)[0]), "r"((a)[1]), "r"((a)[2]), "r"((a)[3]), \
          "r"((b)[0]), "r"((b)[1]))

#define LDSM_X4(r0, r1, r2, r3, addr) \
    asm volatile("ldmatrix.sync.aligned.m8n8.x4.shared.b16 {%0,%1,%2,%3}, [%4];" \
                 : "=r"(r0), "=r"(r1), "=r"(r2), "=r"(r3) : "r"(addr))

#define CP_ASYNC16(smem_addr, gptr) \
    asm volatile("cp.async.cg.shared.global [%0], [%1], 16;" \
                 :: "r"(smem_addr), "l"(gptr) : "memory")
#define CP_ASYNC_WAIT_ALL() \
    asm volatile("cp.async.commit_group;\n\tcp.async.wait_group 0;" ::: "memory")

// ---------------- fused init + weight prep (1 launch) --------------------------
__device__ __forceinline__ void prepW_body(const float* __restrict__ W,
                                           char* __restrict__ hi_img,
                                           char* __restrict__ lo_img,
                                           int i, int BN) {
    if (i >= BN * 32) return;
    int n = i >> 5;
    int k4 = (i & 31) * 4;
    float4 v;
    v.x = W[(size_t)(k4 + 0) * BN + n];
    v.y = W[(size_t)(k4 + 1) * BN + n];
    v.z = W[(size_t)(k4 + 2) * BN + n];
    v.w = W[(size_t)(k4 + 3) * BN + n];
    u64 hi, lo;
    split4(v, hi, lo);
    size_t off = (size_t)n * PITCHB + (size_t)k4 * 2;
    *reinterpret_cast<u64*>(hi_img + off) = hi;
    *reinterpret_cast<u64*>(lo_img + off) = lo;
}

#define NODE_BLOCKS 391   // ceil(100000/256)
__global__ void k_prep_init(const float* __restrict__ W1, const float* __restrict__ W2,
                            const float* __restrict__ W3) {
    int b = blockIdx.x;
    int tid = threadIdx.x;
    if (b < NODE_BLOCKS) {
        int v = b * 256 + tid;
        if (v < NNODES) { g_deg[v] = 1; g_cursor[v] = 0; }
    } else if (b < NODE_BLOCKS + 16) {
        prepW_body(W1, g_W1hi, g_W1lo, (b - NODE_BLOCKS) * 256 + tid, 128);
    } else if (b < NODE_BLOCKS + 32) {
        prepW_body(W2, g_W2hi, g_W2lo, (b - NODE_BLOCKS - 16) * 256 + tid, 128);
    } else {
        prepW_body(W3, g_W3hi, g_W3lo, (b - NODE_BLOCKS - 32) * 256 + tid, 64);
    }
}

// ---------------- mma.sync GEMM (R9 v4 config): fp16 output ------------------
// C[M,BN] = A[M,128] @ W[128,BN]; fused 3-term bf16 split in one K pass.
// 512 thr / 16 warps / BM=64, 2 CTA/SM, warp tile 16 x (BN/4); fp16 epilogue.
template <int BN>
__global__ __launch_bounds__(512, 2) void k_mma(const float* __restrict__ A,
                                                const char* __restrict__ BhiImg,
                                                const char* __restrict__ BloImg,
                                                __half* __restrict__ C, int M) {
    extern __shared__ char smem[];
    constexpr int A_BYTES = 64 * PITCHB;      // 17408
    constexpr int B_BYTES = BN * PITCHB;
    char* sAhi = smem;
    char* sAlo = smem + A_BYTES;
    char* sBhi = smem + 2 * A_BYTES;
    char* sBlo = sBhi + B_BYTES;

    int tid = threadIdx.x;
    int blockRow = blockIdx.x * 64;

    // B-image copy via cp.async (flows under the A load/split below)
    {
        u32 dH = smem_u32(sBhi);
        u32 dL = smem_u32(sBlo);
        for (int i = tid; i < BN * 17; i += 512) {  // BN*272/16
            CP_ASYNC16(dH + i * 16, BhiImg + (size_t)i * 16);
            CP_ASYNC16(dL + i * 16, BloImg + (size_t)i * 16);
        }
    }
    // load + split A tile (64 rows x 128 cols fp32 -> hi/lo bf16)
    for (int i = tid; i < 64 * 32; i += 512) {
        int row = i >> 5;
        int c4 = (i & 31) * 4;
        float4 v = make_float4(0.f, 0.f, 0.f, 0.f);
        int grow = blockRow + row;
        if (grow < M)
            v = *reinterpret_cast<const float4*>(&A[(size_t)grow * 128 + c4]);
        u64 hi, lo;
        split4(v, hi, lo);
        size_t off = (size_t)row * PITCHB + (size_t)c4 * 2;
        *reinterpret_cast<u64*>(sAhi + off) = hi;
        *reinterpret_cast<u64*>(sAlo + off) = lo;
    }
    CP_ASYNC_WAIT_ALL();
    __syncthreads();

    int wid = tid >> 5, lane = tid & 31;
    int g = lane >> 2, t = lane & 3;
    constexpr int WN = BN / 4;        // 32 (BN=128) or 16 (BN=64)
    constexpr int NT = WN / 8;        // 4 or 2
    constexpr int NPAIR = (NT / 2 > 0) ? NT / 2 : 1;  // 2 or 1
    int wm = wid & 3, wn = wid >> 2;
    int rowbase = wm * 16;
    int colbase = wn * WN;

    // ldmatrix lane addressing: row = lane%16, +16B column select for lane>=16
    u32 lrow = lane & 15;
    u32 lsel = (lane >> 4) << 4;
    u32 aHiB = smem_u32(sAhi) + (rowbase + lrow) * PITCHB + lsel;
    u32 aLoB = aHiB + A_BYTES;
    u32 bHiB[NPAIR], bLoB[NPAIR];
#pragma unroll
    for (int p = 0; p < NPAIR; p++) {
        bHiB[p] = smem_u32(sBhi) + (colbase + p * 16 + lrow) * PITCHB + lsel;
        bLoB[p] = bHiB[p] + B_BYTES;
    }

    float c[NT][4];
#pragma unroll
    for (int nt = 0; nt < NT; nt++)
#pragma unroll
        for (int j = 0; j < 4; j++) c[nt][j] = 0.f;

#pragma unroll
    for (int k0 = 0; k0 < 128; k0 += 16) {
        u32 koff = k0 * 2;
        u32 ah[4], al[4];
        LDSM_X4(ah[0], ah[1], ah[2], ah[3], aHiB + koff);
        LDSM_X4(al[0], al[1], al[2], al[3], aLoB + koff);
        u32 bh[NT][2], bl[NT][2];
#pragma unroll
        for (int p = 0; p < NPAIR; p++) {
            u32 r0, r1, r2, r3;
            LDSM_X4(r0, r1, r2, r3, bHiB[p] + koff);
            bh[2 * p + 0][0] = r0; bh[2 * p + 1][0] = r1;
            bh[2 * p + 0][1] = r2; bh[2 * p + 1][1] = r3;
            LDSM_X4(r0, r1, r2, r3, bLoB[p] + koff);
            bl[2 * p + 0][0] = r0; bl[2 * p + 1][0] = r1;
            bl[2 * p + 0][1] = r2; bl[2 * p + 1][1] = r3;
        }
        // 3 terms: hi*hi, hi*lo, lo*hi
#pragma unroll
        for (int nt = 0; nt < NT; nt++) MMA16816(c[nt], ah, bh[nt]);
#pragma unroll
        for (int nt = 0; nt < NT; nt++) MMA16816(c[nt], ah, bl[nt]);
#pragma unroll
        for (int nt = 0; nt < NT; nt++) MMA16816(c[nt], al, bh[nt]);
    }

    // epilogue: fp16 half2 stores (rows g and g+8 of warp tile)
    int row = blockRow + rowbase + g;
#pragma unroll
    for (int nt = 0; nt < NT; nt++) {
        int col = colbase + nt * 8 + 2 * t;
        if (row < M)
            *reinterpret_cast<__half2*>(&C[(size_t)row * BN + col]) =
                __floats2half2_rn(c[nt][0], c[nt][1]);
        if (row + 8 < M)
            *reinterpret_cast<__half2*>(&C[(size_t)(row + 8) * BN + col]) =
                __floats2half2_rn(c[nt][2], c[nt][3]);
    }
}

// ---------------- CSR build ---------------------------------------------------
__global__ void k_count(const int* __restrict__ dst) {
    int e = blockIdx.x * blockDim.x + threadIdx.x;
    if (e < NEDGES) atomicAdd(&g_deg[dst[e]], 1);
}
__global__ void k_scan_block(void) {
    __shared__ int wsum[8];
    int tid = threadIdx.x;
    int base = blockIdx.x * SCAN_CHUNK + tid * 4;
    int v[4];
#pragma unroll
    for (int i = 0; i < 4; i++) {
        int idx = base + i;
        v[i] = (idx < NNODES) ? (g_deg[idx] - 1) : 0;
        if (idx < NNODES) g_dinv[idx] = rsqrtf((float)(v[i] + 1));
    }
    int e0 = 0, e1 = v[0], e2 = v[0] + v[1], e3 = v[0] + v[1] + v[2];
    int tot = e3 + v[3];
    int lane = tid & 31, wid = tid >> 5;
    int x = tot;
#pragma unroll
    for (int off = 1; off < 32; off <<= 1) {
        int y = __shfl_up_sync(0xFFFFFFFFu, x, off);
        if (lane >= off) x += y;
    }
    if (lane == 31) wsum[wid] = x;
    __syncthreads();
    if (wid == 0) {
        int tt = (lane < 8) ? wsum[lane] : 0;
        int xx = tt;
#pragma unroll
        for (int off = 1; off < 8; off <<= 1) {
            int y = __shfl_up_sync(0xFFFFFFFFu, xx, off);
            if (lane >= off) xx += y;
        }
        if (lane < 8) wsum[lane] = xx - tt;
    }
    __syncthreads();
    int texc = wsum[wid] + (x - tot);
    if (base + 0 < NNODES) g_off[base + 0] = texc + e0;
    if (base + 1 < NNODES) g_off[base + 1] = texc + e1;
    if (base + 2 < NNODES) g_off[base + 2] = texc + e2;
    if (base + 3 < NNODES) g_off[base + 3] = texc + e3;
    if (tid == blockDim.x - 1) g_bsum[blockIdx.x] = texc + tot;
}
// scan_add with inlined top-level prefix (each block sums its g_bsum prefix)
__global__ void k_scan_add(void) {
    __shared__ int ssum;
    int tid = threadIdx.x;
    int bid = blockIdx.x;
    if (tid == 0) ssum = 0;
    __syncthreads();
    int p = 0;
    for (int j = tid; j < bid; j += 256) p += g_bsum[j];
    if (p) atomicAdd(&ssum, p);
    __syncthreads();
    int add = ssum;
    int base = bid * SCAN_CHUNK + tid * 4;
#pragma unroll
    for (int i = 0; i < 4; i++) {
        int idx = base + i;
        if (idx < NNODES) g_off[idx] += add;
    }
}
__global__ void k_scatter(const int* __restrict__ src, const int* __restrict__ dst) {
    int e = blockIdx.x * blockDim.x + threadIdx.x;
    if (e >= NEDGES) return;
    int s = src[e], d = dst[e];
    int pos = g_off[d] + atomicAdd(&g_cursor[d], 1);
    g_csr[pos] = make_int2(s, __float_as_int(g_dinv[s] * g_dinv[d]));
}

// ---------------- Aggregation: fp16 gather, fp32 accumulate ------------------
__device__ __forceinline__ float4 h4f(uint2 u) {
    float2 a = __half22float2(*reinterpret_cast<__half2*>(&u.x));
    float2 b = __half22float2(*reinterpret_cast<__half2*>(&u.y));
    return make_float4(a.x, a.y, b.x, b.y);
}
__device__ __forceinline__ float2 h2f(u32 u) {
    return __half22float2(*reinterpret_cast<__half2*>(&u));
}

template <int DIM, bool RELU>
__global__ __launch_bounds__(256) void k_agg(const __half* __restrict__ h,
                                             const float* __restrict__ bias,
                                             float* __restrict__ out) {
    int warp = (blockIdx.x * blockDim.x + threadIdx.x) >> 5;
    if (warp >= NNODES) return;
    int lane = threadIdx.x & 31;

    float dv = g_dinv[warp];
    float wself = dv * dv;
    int beg = g_off[warp];
    int end = beg + (g_deg[warp] - 1);
    const int2* __restrict__ cp = g_csr;

    if (DIM == 128) {
        const uint2* hp = reinterpret_cast<const uint2*>(h);   // 8B = 4 halfs/lane
        float4 sv = h4f(hp[(size_t)warp * 32 + lane]);
        float ax = sv.x * wself, ay = sv.y * wself, az = sv.z * wself, aw = sv.w * wself;
        int e = beg;
        for (; e + 3 < end; e += 4) {
            int2 p0 = cp[e], p1 = cp[e + 1], p2 = cp[e + 2], p3 = cp[e + 3];
            float w0 = __int_as_float(p0.y), w1 = __int_as_float(p1.y);
            float w2 = __int_as_float(p2.y), w3 = __int_as_float(p3.y);
            float4 v0 = h4f(hp[(size_t)p0.x * 32 + lane]);
            float4 v1 = h4f(hp[(size_t)p1.x * 32 + lane]);
            float4 v2 = h4f(hp[(size_t)p2.x * 32 + lane]);
            float4 v3 = h4f(hp[(size_t)p3.x * 32 + lane]);
            ax += v0.x * w0 + v1.x * w1 + v2.x * w2 + v3.x * w3;
            ay += v0.y * w0 + v1.y * w1 + v2.y * w2 + v3.y * w3;
            az += v0.z * w0 + v1.z * w1 + v2.z * w2 + v3.z * w3;
            aw += v0.w * w0 + v1.w * w1 + v2.w * w2 + v3.w * w3;
        }
        for (; e < end; e++) {
            int2 p0 = cp[e];
            float w0 = __int_as_float(p0.y);
            float4 v0 = h4f(hp[(size_t)p0.x * 32 + lane]);
            ax += v0.x * w0; ay += v0.y * w0; az += v0.z * w0; aw += v0.w * w0;
        }
        float4 b4 = reinterpret_cast<const float4*>(bias)[lane];
        ax += b4.x; ay += b4.y; az += b4.z; aw += b4.w;
        if (RELU) {
            ax = fmaxf(ax, 0.f); ay = fmaxf(ay, 0.f);
            az = fmaxf(az, 0.f); aw = fmaxf(aw, 0.f);
        }
        float4 o; o.x = ax; o.y = ay; o.z = az; o.w = aw;
        reinterpret_cast<float4*>(out)[(size_t)warp * 32 + lane] = o;
    } else {  // DIM == 64
        const u32* hp = reinterpret_cast<const u32*>(h);       // 4B = 2 halfs/lane
        float2 sv = h2f(hp[(size_t)warp * 32 + lane]);
        float ax = sv.x * wself, ay = sv.y * wself;
        int e = beg;
        for (; e + 3 < end; e += 4) {
            int2 p0 = cp[e], p1 = cp[e + 1], p2 = cp[e + 2], p3 = cp[e + 3];
            float w0 = __int_as_float(p0.y), w1 = __int_as_float(p1.y);
            float w2 = __int_as_float(p2.y), w3 = __int_as_float(p3.y);
            float2 v0 = h2f(hp[(size_t)p0.x * 32 + lane]);
            float2 v1 = h2f(hp[(size_t)p1.x * 32 + lane]);
            float2 v2 = h2f(hp[(size_t)p2.x * 32 + lane]);
            float2 v3 = h2f(hp[(size_t)p3.x * 32 + lane]);
            ax += v0.x * w0 + v1.x * w1 + v2.x * w2 + v3.x * w3;
            ay += v0.y * w0 + v1.y * w1 + v2.y * w2 + v3.y * w3;
        }
        for (; e < end; e++) {
            int2 p0 = cp[e];
            float w0 = __int_as_float(p0.y);
            float2 v0 = h2f(hp[(size_t)p0.x * 32 + lane]);
            ax += v0.x * w0; ay += v0.y * w0;
        }
        float2 b2 = reinterpret_cast<const float2*>(bias)[lane];
        ax += b2.x; ay += b2.y;
        if (RELU) { ax = fmaxf(ax, 0.f); ay = fmaxf(ay, 0.f); }
        float2 o; o.x = ax; o.y = ay;
        reinterpret_cast<float2*>(out)[(size_t)warp * 32 + lane] = o;
    }
}

// ---------------- launch ------------------------------------------------------
extern "C" void kernel_launch(void* const* d_in, const int* in_sizes, int n_in,
                              void* d_out, int out_size) {
    const float* x  = (const float*)d_in[0];
    const int*   ei = (const int*)d_in[1];
    const float* W1 = (const float*)d_in[2];
    const float* b1 = (const float*)d_in[3];
    const float* W2 = (const float*)d_in[4];
    const float* b2 = (const float*)d_in[5];
    const float* W3 = (const float*)d_in[6];
    const float* b3 = (const float*)d_in[7];
    float* out = (float*)d_out;

    const int* src = ei;
    const int* dst = ei + NEDGES;

    __half* bufT; cudaGetSymbolAddress((void**)&bufT, g_bufT);
    float*  bufB; cudaGetSymbolAddress((void**)&bufB, g_bufB);
    char *w1h, *w1l, *w2h, *w2l, *w3h, *w3l;
    cudaGetSymbolAddress((void**)&w1h, g_W1hi); cudaGetSymbolAddress((void**)&w1l, g_W1lo);
    cudaGetSymbolAddress((void**)&w2h, g_W2hi); cudaGetSymbolAddress((void**)&w2l, g_W2lo);
    cudaGetSymbolAddress((void**)&w3h, g_W3hi); cudaGetSymbolAddress((void**)&w3l, g_W3lo);

    const int SMEM128 = 2 * 64 * PITCHB + 2 * 128 * PITCHB;  // 104448
    const int SMEM64  = 2 * 64 * PITCHB + 2 * 64 * PITCHB;   //  69632
    cudaFuncSetAttribute(k_mma<128>, cudaFuncAttributeMaxDynamicSharedMemorySize, SMEM128);
    cudaFuncSetAttribute(k_mma<64>,  cudaFuncAttributeMaxDynamicSharedMemorySize, SMEM64);

    const int TB = 256;
    int edgeBlocks = (NEDGES + TB - 1) / TB;
    int gemmBlocks = (NNODES + 63) / 64;     // 1563
    int aggBlocks  = (NNODES + 7) / 8;
    int prepBlocks = NODE_BLOCKS + 16 + 16 + 8;  // 431

    // Capture-forked side stream for the CSR chain (overlaps prep+GEMM1).
    // Lazily created on the first (uncaptured) correctness call; reused during
    // graph capture, where event record/wait become graph dependencies.
    static cudaStream_t s2 = nullptr;
    static cudaEvent_t evFork = nullptr, evJoin = nullptr;
    if (s2 == nullptr) {
        cudaStreamCreateWithFlags(&s2, cudaStreamNonBlocking);
        cudaEventCreateWithFlags(&evFork, cudaEventDisableTiming);
        cudaEventCreateWithFlags(&evJoin, cudaEventDisableTiming);
    }

    // main stream: prep -> GEMM1 ; side stream: count -> scan -> scan_add -> scatter
    k_prep_init<<<prepBlocks, TB>>>(W1, W2, W3);                       // #1
    cudaEventRecord(evFork, 0);
    cudaStreamWaitEvent(s2, evFork, 0);
    k_count<<<edgeBlocks, TB, 0, s2>>>(dst);                           // #2
    k_scan_block<<<SCAN_BLOCKS, TB, 0, s2>>>();                        // #3 (fills g_dinv)
    k_mma<128><<<gemmBlocks, 512, SMEM128>>>(x, w1h, w1l, bufT, NNODES); // #4 (profiled)
    k_scan_add<<<SCAN_BLOCKS, TB, 0, s2>>>();                          // #5
    k_scatter<<<edgeBlocks, TB, 0, s2>>>(src, dst);                    // #6
    cudaEventRecord(evJoin, s2);
    cudaStreamWaitEvent(0, evJoin, 0);

    // serial remainder (each depends on the previous)
    k_agg<128, true><<<aggBlocks, TB>>>(bufT, b1, bufB);
    k_mma<128><<<gemmBlocks, 512, SMEM128>>>(bufB, w2h, w2l, bufT, NNODES);
    k_agg<128, true><<<aggBlocks, TB>>>(bufT, b2, bufB);
    k_mma<64><<<gemmBlocks, 512, SMEM64>>>(bufB, w3h, w3l, bufT, NNODES);
    k_agg<64, false><<<aggBlocks, TB>>>(bufT, b3, out);
}